// round 14
// baseline (speedup 1.0000x reference)
#include <cuda_runtime.h>
#include <math.h>

#define NP2 64
#define NV  32768
#define WPB 4            // warps per block
#define VPW 4            // voxels per warp
// 8 lanes per voxel, 4 k-states per lane, INTERLEAVED pairs:
// pair a = (k0,k2), pair b = (k1,k3)  ->  k-shift is a pair swap + 1 pack.

typedef unsigned long long u64;

// Per-pulse coefficients, pre-broadcast as {x,x} f32 pairs.
// [p][0]={ca,sa} [p][1]={-sa,cd} [p][2]={sd,-sd}
__device__ ulonglong2 g_cf[NP2][3];

__device__ __forceinline__ u64 dup_(float x) {
    u64 r; asm("mov.b64 %0,{%1,%1};" : "=l"(r) : "f"(x)); return r;
}

__global__ void precompute_coef_kernel(const float* __restrict__ thr,
                                       const float* __restrict__ thi) {
    int p = threadIdx.x;
    if (p >= NP2) return;
    float tr = thr[p], ti = thi[p];
    float a  = sqrtf(tr * tr + ti * ti);       // |theta| in (0.1, pi/2): never 0
    float inv_a = 1.0f / a;
    float cphi = tr * inv_a, sphi = ti * inv_a;
    float ca, sa;
    sincosf(a, &sa, &ca);

    // next pulse phase (delta twist); last pulse: delta = 0
    int pn = (p + 1 < NP2) ? p + 1 : p;
    float trn = thr[pn], tin = thi[pn];
    float an = sqrtf(trn * trn + tin * tin);
    float inv_an = 1.0f / an;
    float cphin = trn * inv_an, sphin = tin * inv_an;
    float cd = cphi * cphin + sphi * sphin;    // cos(phi_p - phi_{p+1})
    float sd = sphi * cphin - cphi * sphin;    // sin(phi_p - phi_{p+1})
    if (p + 1 >= NP2) { cd = 1.0f; sd = 0.0f; }

    g_cf[p][0] = make_ulonglong2(dup_(ca),  dup_(sa));
    g_cf[p][1] = make_ulonglong2(dup_(-sa), dup_(cd));
    g_cf[p][2] = make_ulonglong2(dup_(sd),  dup_(-sd));
}

// ---- packed f32x2 helpers ----
__device__ __forceinline__ u64 bc(float x) {
    u64 r; asm("mov.b64 %0,{%1,%1};" : "=l"(r) : "f"(x)); return r;
}
__device__ __forceinline__ u64 pk(float a, float b) {
    u64 r; asm("mov.b64 %0,{%1,%2};" : "=l"(r) : "f"(a), "f"(b)); return r;
}
__device__ __forceinline__ float lo_(u64 v) {
    float a, b; asm("mov.b64 {%0,%1},%2;" : "=f"(a), "=f"(b) : "l"(v)); return a;
}
__device__ __forceinline__ float hi_(u64 v) {
    float a, b; asm("mov.b64 {%0,%1},%2;" : "=f"(a), "=f"(b) : "l"(v)); return b;
}
__device__ __forceinline__ u64 f2(u64 a, u64 b, u64 c) {
    u64 d; asm("fma.rn.f32x2 %0,%1,%2,%3;" : "=l"(d) : "l"(a), "l"(b), "l"(c)); return d;
}
__device__ __forceinline__ u64 m2(u64 a, u64 b) {
    u64 d; asm("mul.rn.f32x2 %0,%1,%2;" : "=l"(d) : "l"(a), "l"(b)); return d;
}
__device__ __forceinline__ u64 s2(u64 a, u64 b) {
    u64 d; asm("sub.rn.f32x2 %0,%1,%2;" : "=l"(d) : "l"(a), "l"(b)); return d;
}
__device__ __forceinline__ u64 a2(u64 a, u64 b) {
    u64 d; asm("add.rn.f32x2 %0,%1,%2;" : "=l"(d) : "l"(a), "l"(b)); return d;
}

// hS/hD-form matvec core (transverse only; Z handled separately with E1 fold):
//   w  = ca*hDr + sa*Zi,  vi = ca*hSi - sa*Zr
//   tP = hSr+w | vi+hDi,  tN = hSr-w | vi-hDi
#define MATVEC(S) \
  u64 w_##S   = f2(Cca, hDr_##S, m2(Csa, Zi_##S)); \
  u64 vi_##S  = f2(Cca, hSi_##S, m2(Cnsa, Zr_##S)); \
  u64 tPr_##S = a2(hSr_##S, w_##S); \
  u64 tNr_##S = s2(hSr_##S, w_##S); \
  u64 tPi_##S = a2(vi_##S, hDi_##S); \
  u64 tNi_##S = s2(vi_##S, hDi_##S);

// 4 voxels per warp, 8 lanes per voxel, 4 k-states per lane (interleaved).
__global__ __launch_bounds__(WPB * 32, 8)
void epg_kernel(const float* __restrict__ qmaps,   // [3, V]: PD, T1, T2
                const float* __restrict__ TRp,
                float* __restrict__ out) {          // [V, NP2]
    __shared__ ulonglong2 scf[NP2][3];              // 3KB coefficient table
    __shared__ float2 f0s[WPB][VPW][NP2 + 1];

    const int tid   = threadIdx.x;
    const int lane  = tid & 31;
    const int wid   = tid >> 5;
    const int sub   = lane >> 3;                    // voxel within warp
    const int ll    = lane & 7;                     // lane within voxel
    const int vbase = blockIdx.x * (WPB * VPW) + wid * VPW;
    const int v     = vbase + sub;
    const bool l0 = (ll == 0), l7 = (ll == 7);

    // cooperative copy of the coefficient table (192 entries, 128 threads)
    {
        const ulonglong2* src = &g_cf[0][0];
        ulonglong2* dst = &scf[0][0];
        for (int i = tid; i < NP2 * 3; i += WPB * 32) dst[i] = src[i];
    }

    const float TR = TRp[0];
    const float E1 = __expf(-TR / qmaps[NV + v]);
    const float E2 = __expf(-TR / qmaps[2 * NV + v]);
    const u64 E1p = bc(E1), E2h = bc(0.5f * E2);
    const u64 RecA = pk(l0 ? (1.0f - E1) : 0.0f, 0.0f);

    // State: hS=(P+N)/2, hD=(P-N)/2, Z; pair a=(k0,k2), pair b=(k1,k3).
    u64 hSr_a = 0, hSr_b = 0, hSi_a = 0, hSi_b = 0;
    u64 hDr_a = 0, hDr_b = 0, hDi_a = 0, hDi_b = 0;
    u64 Zr_a = pk(l0 ? 1.0f : 0.0f, 0.0f), Zr_b = 0, Zi_a = 0, Zi_b = 0;

    __syncthreads();

    #pragma unroll 16
    for (int p = 0; p < NP2; p++) {
        const ulonglong2 q0 = scf[p][0];
        const ulonglong2 q1 = scf[p][1];
        const ulonglong2 q2 = scf[p][2];
        const u64 Cca  = q0.x, Csa  = q0.y;
        const u64 Cnsa = q1.x;
        // uh = (E2/2) * e^{i(phi_p - phi_{p+1})}
        const u64 Uhr  = m2(E2h, q1.y);
        const u64 Uhi  = m2(E2h, q2.x);
        const u64 NUhi = m2(E2h, q2.y);
        // E1-folded Z rotation coefficients
        const u64 caE1  = m2(Cca,  E1p);
        const u64 saE1  = m2(Csa,  E1p);
        const u64 nsaE1 = m2(Cnsa, E1p);

        MATVEC(a)
        MATVEC(b)

        // Z' = E1*(ca*Z + sa*(hSi | -hDr)) + Rec   (uses PRE-shift hSi/hDr)
        Zr_a = f2(caE1, Zr_a, f2(saE1, hSi_a, RecA));
        Zi_a = f2(caE1, Zi_a, m2(nsaE1, hDr_a));
        Zr_b = f2(caE1, Zr_b, m2(saE1, hSi_b));
        Zi_b = f2(caE1, Zi_b, m2(nsaE1, hDr_b));

        // F0 = tP at k=0 pre-shift (pair a lo); frame phase drops under |.|
        if (l0) f0s[wid][sub][p] = make_float2(lo_(tPr_a), lo_(tPi_a));

        // EPG shift with interleaved pairs:
        //  P up:  new_a=(in, old k1)=(in, tP_b.lo); new_b=(old k0, old k2)=tP_a
        //  N dn:  new_a=(old k1, old k3)=tN_b;      new_b=(old k2, in)=(tN_a.hi, in)
        // boundary: P_0 <- tN at k1 = tN_b.lo (own thread); N_31 <- 0.
        float sPr = hi_(tPr_b), sPi = hi_(tPi_b);          // outgoing k3
        float sNr = lo_(tNr_a), sNi = lo_(tNi_a);          // outgoing k0
        float inPr = __shfl_up_sync(0xffffffffu, sPr, 1);
        float inPi = __shfl_up_sync(0xffffffffu, sPi, 1);
        float inNr = __shfl_down_sync(0xffffffffu, sNr, 1);
        float inNi = __shfl_down_sync(0xffffffffu, sNi, 1);
        if (l0) { inPr = lo_(tNr_b); inPi = lo_(tNi_b); }
        if (l7) { inNr = 0.0f; inNi = 0.0f; }

        const u64 Xr_a = pk(inPr, lo_(tPr_b)), Xr_b = tPr_a;
        const u64 Xi_a = pk(inPi, lo_(tPi_b)), Xi_b = tPi_a;
        const u64 Yr_a = tNr_b, Yr_b = pk(hi_(tNr_a), inNr);
        const u64 Yi_a = tNi_b, Yi_b = pk(hi_(tNi_a), inNi);

        // sums/diffs, then twist-relax: hS' = uh*(X+Y), hD' = uh*(X-Y)
        const u64 Ar_a = a2(Xr_a, Yr_a), Ar_b = a2(Xr_b, Yr_b);
        const u64 Ai_a = a2(Xi_a, Yi_a), Ai_b = a2(Xi_b, Yi_b);
        const u64 Br_a = s2(Xr_a, Yr_a), Br_b = s2(Xr_b, Yr_b);
        const u64 Bi_a = s2(Xi_a, Yi_a), Bi_b = s2(Xi_b, Yi_b);

        hSr_a = f2(Uhr, Ar_a, m2(NUhi, Ai_a));  hSr_b = f2(Uhr, Ar_b, m2(NUhi, Ai_b));
        hSi_a = f2(Uhr, Ai_a, m2(Uhi , Ar_a));  hSi_b = f2(Uhr, Ai_b, m2(Uhi , Ar_b));
        hDr_a = f2(Uhr, Br_a, m2(NUhi, Bi_a));  hDr_b = f2(Uhr, Br_b, m2(NUhi, Bi_b));
        hDi_a = f2(Uhr, Bi_a, m2(Uhi , Br_a));  hDi_b = f2(Uhr, Bi_b, m2(Uhi , Br_b));
    }

    __syncwarp();

    // Epilogue: |F0| * PD; 4 consecutive voxels per warp -> coalesced stores
    const float* pdp = qmaps + vbase;
    float* ob = out + (size_t)vbase * NP2;
    #pragma unroll
    for (int i = 0; i < (VPW * NP2) / 32; i++) {
        int flat = i * 32 + lane;
        int vv   = flat >> 6;
        int idx  = flat & 63;
        float2 f = f0s[wid][vv][idx];
        ob[flat] = sqrtf(f.x * f.x + f.y * f.y) * pdp[vv];
    }
}

extern "C" void kernel_launch(void* const* d_in, const int* in_sizes, int n_in,
                              void* d_out, int out_size) {
    const float* theta_re = (const float*)d_in[0];   // [64]
    const float* theta_im = (const float*)d_in[1];   // [64]
    const float* TR       = (const float*)d_in[2];   // [1]
    const float* qmaps    = (const float*)d_in[3];   // [3, 32768, 1]
    float* out = (float*)d_out;                      // [32768, 64]

    precompute_coef_kernel<<<1, 64>>>(theta_re, theta_im);
    epg_kernel<<<NV / (WPB * VPW), WPB * 32>>>(qmaps, TR, out);
}

// round 15
// speedup vs baseline: 1.0315x; 1.0315x over previous
#include <cuda_runtime.h>
#include <math.h>

#define NP2 64
#define NV  32768
#define WPB 4            // warps per block
#define VPW 4            // voxels per warp
// 8 lanes per voxel, 4 k-states per lane, INTERLEAVED pairs:
// pair a = (k0,k2), pair b = (k1,k3)  ->  k-shift is a pair swap + 1 pack.

typedef unsigned long long u64;

// ---- packed f32x2 helpers ----
__device__ __forceinline__ u64 bc(float x) {
    u64 r; asm("mov.b64 %0,{%1,%1};" : "=l"(r) : "f"(x)); return r;
}
__device__ __forceinline__ u64 pk(float a, float b) {
    u64 r; asm("mov.b64 %0,{%1,%2};" : "=l"(r) : "f"(a), "f"(b)); return r;
}
__device__ __forceinline__ float lo_(u64 v) {
    float a, b; asm("mov.b64 {%0,%1},%2;" : "=f"(a), "=f"(b) : "l"(v)); return a;
}
__device__ __forceinline__ float hi_(u64 v) {
    float a, b; asm("mov.b64 {%0,%1},%2;" : "=f"(a), "=f"(b) : "l"(v)); return b;
}
__device__ __forceinline__ u64 f2(u64 a, u64 b, u64 c) {
    u64 d; asm("fma.rn.f32x2 %0,%1,%2,%3;" : "=l"(d) : "l"(a), "l"(b), "l"(c)); return d;
}
__device__ __forceinline__ u64 m2(u64 a, u64 b) {
    u64 d; asm("mul.rn.f32x2 %0,%1,%2;" : "=l"(d) : "l"(a), "l"(b)); return d;
}
__device__ __forceinline__ u64 s2(u64 a, u64 b) {
    u64 d; asm("sub.rn.f32x2 %0,%1,%2;" : "=l"(d) : "l"(a), "l"(b)); return d;
}
__device__ __forceinline__ u64 a2(u64 a, u64 b) {
    u64 d; asm("add.rn.f32x2 %0,%1,%2;" : "=l"(d) : "l"(a), "l"(b)); return d;
}

// hS/hD-form matvec core (transverse only; Z handled separately with E1 fold):
//   w  = ca*hDr + sa*Zi,  vi = ca*hSi - sa*Zr
//   tP = hSr+w | vi+hDi,  tN = hSr-w | vi-hDi
#define MATVEC(S) \
  u64 w_##S   = f2(Cca, hDr_##S, m2(Csa, Zi_##S)); \
  u64 vi_##S  = f2(Cca, hSi_##S, m2(Cnsa, Zr_##S)); \
  u64 tPr_##S = a2(hSr_##S, w_##S); \
  u64 tNr_##S = s2(hSr_##S, w_##S); \
  u64 tPi_##S = a2(vi_##S, hDi_##S); \
  u64 tNi_##S = s2(vi_##S, hDi_##S);

// 4 voxels per warp, 8 lanes per voxel, 4 k-states per lane (interleaved).
// Coefficients computed IN-KERNEL (no separate precompute launch).
__global__ __launch_bounds__(WPB * 32, 8)
void epg_kernel(const float* __restrict__ thr,     // theta_re [NP2]
                const float* __restrict__ thi,     // theta_im [NP2]
                const float* __restrict__ qmaps,   // [3, V]: PD, T1, T2
                const float* __restrict__ TRp,
                float* __restrict__ out) {          // [V, NP2]
    __shared__ ulonglong2 scf[NP2][3];              // 3KB coefficient table
    __shared__ float2 f0s[WPB][VPW][NP2 + 1];

    const int tid   = threadIdx.x;
    const int lane  = tid & 31;
    const int wid   = tid >> 5;
    const int sub   = lane >> 3;                    // voxel within warp
    const int ll    = lane & 7;                     // lane within voxel
    const int vbase = blockIdx.x * (WPB * VPW) + wid * VPW;
    const int v     = vbase + sub;
    const bool l0 = (ll == 0), l7 = (ll == 7);

    // In-block coefficient computation: thread p (<NP2) fills pulse p.
    // [p][0]={ca,sa} [p][1]={-sa,cd} [p][2]={sd,-sd}
    if (tid < NP2) {
        const int p = tid;
        float tr = thr[p], ti = thi[p];
        float a  = sqrtf(tr * tr + ti * ti);   // |theta| in (0.1, pi/2): never 0
        float inv_a = 1.0f / a;
        float cphi = tr * inv_a, sphi = ti * inv_a;
        float ca, sa;
        sincosf(a, &sa, &ca);

        // next pulse phase (delta twist); last pulse: delta = 0
        int pn = (p + 1 < NP2) ? p + 1 : p;
        float trn = thr[pn], tin = thi[pn];
        float an = sqrtf(trn * trn + tin * tin);
        float inv_an = 1.0f / an;
        float cphin = trn * inv_an, sphin = tin * inv_an;
        float cd = cphi * cphin + sphi * sphin;    // cos(phi_p - phi_{p+1})
        float sd = sphi * cphin - cphi * sphin;    // sin(phi_p - phi_{p+1})
        if (p + 1 >= NP2) { cd = 1.0f; sd = 0.0f; }

        scf[p][0] = make_ulonglong2(bc(ca),  bc(sa));
        scf[p][1] = make_ulonglong2(bc(-sa), bc(cd));
        scf[p][2] = make_ulonglong2(bc(sd),  bc(-sd));
    }

    const float TR = TRp[0];
    const float E1 = __expf(-TR / qmaps[NV + v]);
    const float E2 = __expf(-TR / qmaps[2 * NV + v]);
    const u64 E1p = bc(E1), E2h = bc(0.5f * E2);
    const u64 RecA = pk(l0 ? (1.0f - E1) : 0.0f, 0.0f);

    // State: hS=(P+N)/2, hD=(P-N)/2, Z; pair a=(k0,k2), pair b=(k1,k3).
    u64 hSr_a = 0, hSr_b = 0, hSi_a = 0, hSi_b = 0;
    u64 hDr_a = 0, hDr_b = 0, hDi_a = 0, hDi_b = 0;
    u64 Zr_a = pk(l0 ? 1.0f : 0.0f, 0.0f), Zr_b = 0, Zi_a = 0, Zi_b = 0;

    __syncthreads();

    #pragma unroll 16
    for (int p = 0; p < NP2; p++) {
        const ulonglong2 q0 = scf[p][0];
        const ulonglong2 q1 = scf[p][1];
        const ulonglong2 q2 = scf[p][2];
        const u64 Cca  = q0.x, Csa  = q0.y;
        const u64 Cnsa = q1.x;
        // uh = (E2/2) * e^{i(phi_p - phi_{p+1})}
        const u64 Uhr  = m2(E2h, q1.y);
        const u64 Uhi  = m2(E2h, q2.x);
        const u64 NUhi = m2(E2h, q2.y);
        // E1-folded Z rotation coefficients
        const u64 caE1  = m2(Cca,  E1p);
        const u64 saE1  = m2(Csa,  E1p);
        const u64 nsaE1 = m2(Cnsa, E1p);

        MATVEC(a)
        MATVEC(b)

        // Z' = E1*(ca*Z + sa*(hSi | -hDr)) + Rec   (uses PRE-shift hSi/hDr)
        Zr_a = f2(caE1, Zr_a, f2(saE1, hSi_a, RecA));
        Zi_a = f2(caE1, Zi_a, m2(nsaE1, hDr_a));
        Zr_b = f2(caE1, Zr_b, m2(saE1, hSi_b));
        Zi_b = f2(caE1, Zi_b, m2(nsaE1, hDr_b));

        // F0 = tP at k=0 pre-shift (pair a lo); frame phase drops under |.|
        if (l0) f0s[wid][sub][p] = make_float2(lo_(tPr_a), lo_(tPi_a));

        // EPG shift with interleaved pairs:
        //  P up:  new_a=(in, old k1)=(in, tP_b.lo); new_b=(old k0, old k2)=tP_a
        //  N dn:  new_a=(old k1, old k3)=tN_b;      new_b=(old k2, in)=(tN_a.hi, in)
        // boundary: P_0 <- tN at k1 = tN_b.lo (own thread); N_31 <- 0.
        float sPr = hi_(tPr_b), sPi = hi_(tPi_b);          // outgoing k3
        float sNr = lo_(tNr_a), sNi = lo_(tNi_a);          // outgoing k0
        float inPr = __shfl_up_sync(0xffffffffu, sPr, 1);
        float inPi = __shfl_up_sync(0xffffffffu, sPi, 1);
        float inNr = __shfl_down_sync(0xffffffffu, sNr, 1);
        float inNi = __shfl_down_sync(0xffffffffu, sNi, 1);
        if (l0) { inPr = lo_(tNr_b); inPi = lo_(tNi_b); }
        if (l7) { inNr = 0.0f; inNi = 0.0f; }

        const u64 Xr_a = pk(inPr, lo_(tPr_b)), Xr_b = tPr_a;
        const u64 Xi_a = pk(inPi, lo_(tPi_b)), Xi_b = tPi_a;
        const u64 Yr_a = tNr_b, Yr_b = pk(hi_(tNr_a), inNr);
        const u64 Yi_a = tNi_b, Yi_b = pk(hi_(tNi_a), inNi);

        // sums/diffs, then twist-relax: hS' = uh*(X+Y), hD' = uh*(X-Y)
        const u64 Ar_a = a2(Xr_a, Yr_a), Ar_b = a2(Xr_b, Yr_b);
        const u64 Ai_a = a2(Xi_a, Yi_a), Ai_b = a2(Xi_b, Yi_b);
        const u64 Br_a = s2(Xr_a, Yr_a), Br_b = s2(Xr_b, Yr_b);
        const u64 Bi_a = s2(Xi_a, Yi_a), Bi_b = s2(Xi_b, Yi_b);

        hSr_a = f2(Uhr, Ar_a, m2(NUhi, Ai_a));  hSr_b = f2(Uhr, Ar_b, m2(NUhi, Ai_b));
        hSi_a = f2(Uhr, Ai_a, m2(Uhi , Ar_a));  hSi_b = f2(Uhr, Ai_b, m2(Uhi , Ar_b));
        hDr_a = f2(Uhr, Br_a, m2(NUhi, Bi_a));  hDr_b = f2(Uhr, Br_b, m2(NUhi, Bi_b));
        hDi_a = f2(Uhr, Bi_a, m2(Uhi , Br_a));  hDi_b = f2(Uhr, Bi_b, m2(Uhi , Br_b));
    }

    __syncwarp();

    // Epilogue: |F0| * PD; 4 consecutive voxels per warp -> coalesced stores
    const float* pdp = qmaps + vbase;
    float* ob = out + (size_t)vbase * NP2;
    #pragma unroll
    for (int i = 0; i < (VPW * NP2) / 32; i++) {
        int flat = i * 32 + lane;
        int vv   = flat >> 6;
        int idx  = flat & 63;
        float2 f = f0s[wid][vv][idx];
        ob[flat] = sqrtf(f.x * f.x + f.y * f.y) * pdp[vv];
    }
}

extern "C" void kernel_launch(void* const* d_in, const int* in_sizes, int n_in,
                              void* d_out, int out_size) {
    const float* theta_re = (const float*)d_in[0];   // [64]
    const float* theta_im = (const float*)d_in[1];   // [64]
    const float* TR       = (const float*)d_in[2];   // [1]
    const float* qmaps    = (const float*)d_in[3];   // [3, 32768, 1]
    float* out = (float*)d_out;                      // [32768, 64]

    epg_kernel<<<NV / (WPB * VPW), WPB * 32>>>(theta_re, theta_im, qmaps, TR, out);
}